// round 1
// baseline (speedup 1.0000x reference)
#include <cuda_runtime.h>
#include <math.h>

#define BB 16
#define LL 2048
#define DIN 64
#define HH 256
#define NH 32
#define NLAYERS 4
#define DM1 128
#define DM2 64
#define DOUT 32

// Scratch (allocation-free contract: __device__ globals)
__device__ float g_h [BB*LL*HH];   // current hidden state, layout (B, L, H)
__device__ float g_yg[BB*LL*HH];   // gelu(conv + skip)
__device__ float g_zr[BB*LL*HH];   // glu + residual (pre-LN)
__device__ float g_pool[BB*HH];

// ---------------------------------------------------------------------------
// Encoder: g_h[m, n] = x[m, :64] @ enc_w[:, n] + enc_b[n],  m = b*L + l
// Tiles: BM=64, BN=64, BK=32; 256 threads; 4x4 per thread.
// ---------------------------------------------------------------------------
__global__ __launch_bounds__(256) void encoder_kernel(
        const float* __restrict__ X, const float* __restrict__ W,
        const float* __restrict__ bias) {
    __shared__ float As[64][36];   // [row][k]
    __shared__ float Bs[32][68];   // [k][n]
    int row0 = blockIdx.x * 64;
    int n0   = blockIdx.y * 64;
    int tid = threadIdx.x;
    int tx = tid & 15, ty = tid >> 4;
    float acc[4][4] = {};
    for (int k0 = 0; k0 < DIN; k0 += 32) {
        #pragma unroll
        for (int p = 0; p < 2; p++) {
            int q = tid + p * 256;          // 512 quads: 64 rows x 8 quads
            int r = q >> 3, kq = q & 7;
            float4 v = *(const float4*)&X[(row0 + r) * DIN + k0 + kq * 4];
            *(float4*)&As[r][kq * 4] = v;
        }
        #pragma unroll
        for (int p = 0; p < 2; p++) {
            int q = tid + p * 256;          // 512 quads: 32 k-rows x 16 quads
            int kk = q >> 4, nq = q & 15;
            float4 v = *(const float4*)&W[(k0 + kk) * HH + n0 + nq * 4];
            *(float4*)&Bs[kk][nq * 4] = v;
        }
        __syncthreads();
        #pragma unroll
        for (int k = 0; k < 32; k++) {
            float a[4];
            #pragma unroll
            for (int i = 0; i < 4; i++) a[i] = As[ty * 4 + i][k];
            float4 bv = *(const float4*)&Bs[k][tx * 4];
            float bj[4] = {bv.x, bv.y, bv.z, bv.w};
            #pragma unroll
            for (int i = 0; i < 4; i++)
                #pragma unroll
                for (int j = 0; j < 4; j++)
                    acc[i][j] = fmaf(a[i], bj[j], acc[i][j]);
        }
        __syncthreads();
    }
    #pragma unroll
    for (int i = 0; i < 4; i++) {
        int m = row0 + ty * 4 + i;
        #pragma unroll
        for (int j = 0; j < 4; j++) {
            int n = n0 + tx * 4 + j;
            g_h[m * HH + n] = acc[i][j] + bias[n];
        }
    }
}

// ---------------------------------------------------------------------------
// S4D scan: per channel (b,h), 32 complex states. Warp handles 4 channels
// (8 lanes each, 4 states per lane).  Fused: y = gelu(conv + h*D_skip).
// grid (B, H/16), block 128 (16 channels per block).
// ---------------------------------------------------------------------------
#define SCAN_T 128
__global__ __launch_bounds__(128) void scan_kernel(
        const float* __restrict__ log_dt, const float* __restrict__ C_re,
        const float* __restrict__ C_im,   const float* __restrict__ log_A_real,
        const float* __restrict__ A_imag, const float* __restrict__ D_skip,
        int layer) {
    __shared__ float s_in [SCAN_T * 16];
    __shared__ float s_out[SCAN_T * 16];
    int b   = blockIdx.x;
    int ch0 = blockIdx.y * 16;
    int tid = threadIdx.x;
    int warp = tid >> 5, lane = tid & 31;
    int g = lane >> 3, j = lane & 7;
    int c_local = warp * 4 + g;
    int ch = ch0 + c_local;

    float dt  = expf(log_dt[layer * HH + ch]);
    float dsk = D_skip[layer * HH + ch];
    float w_re[4], w_im[4], ck_re[4], ck_im[4], s_re[4], s_im[4];
    #pragma unroll
    for (int k = 0; k < 4; k++) {
        int n = j * 4 + k;
        int idx = (layer * HH + ch) * NH + n;
        float Are = -expf(log_A_real[idx]);
        float Aim = A_imag[idx];
        float er  = expf(dt * Are);
        float wre = er * cosf(dt * Aim);
        float wim = er * sinf(dt * Aim);
        w_re[k] = wre; w_im[k] = wim;
        float nre = wre - 1.0f, nim = wim;
        float inv = 1.0f / (Are * Are + Aim * Aim);
        float ire = Are * inv, iim = -Aim * inv;       // 1/A = conj(A)/|A|^2
        float tre = nre * ire - nim * iim;
        float tim = nre * iim + nim * ire;
        float cre = C_re[idx], cim = C_im[idx];
        ck_re[k] = 2.0f * (cre * tre - cim * tim);
        ck_im[k] = 2.0f * (cre * tim + cim * tre);
        s_re[k] = 0.0f; s_im[k] = 0.0f;
    }

    const float* hin  = g_h  + (size_t)b * LL * HH;
    float*       yout = g_yg + (size_t)b * LL * HH;

    for (int l0 = 0; l0 < LL; l0 += SCAN_T) {
        #pragma unroll
        for (int p = 0; p < 4; p++) {
            int q = tid + p * 128;              // 512 quads: 128 t x 4 quads
            int t = q >> 2, cq = q & 3;
            float4 v = *(const float4*)&hin[(l0 + t) * HH + ch0 + cq * 4];
            *(float4*)&s_in[t * 16 + cq * 4] = v;
        }
        __syncthreads();
        #pragma unroll 4
        for (int t = 0; t < SCAN_T; t++) {
            float u = s_in[t * 16 + c_local];   // broadcast within lane group
            float pacc = 0.0f;
            #pragma unroll
            for (int k = 0; k < 4; k++) {
                float nr = fmaf(w_re[k], s_re[k], u);
                nr = fmaf(-w_im[k], s_im[k], nr);
                float ni = w_re[k] * s_im[k];
                ni = fmaf(w_im[k], s_re[k], ni);
                s_re[k] = nr; s_im[k] = ni;
                pacc = fmaf(ck_re[k], nr, pacc);
                pacc = fmaf(-ck_im[k], ni, pacc);
            }
            pacc += __shfl_xor_sync(0xffffffffu, pacc, 1);
            pacc += __shfl_xor_sync(0xffffffffu, pacc, 2);
            pacc += __shfl_xor_sync(0xffffffffu, pacc, 4);
            if (j == 0)
                s_out[t * 16 + c_local] = fmaf(u, dsk, pacc);
        }
        __syncthreads();
        #pragma unroll
        for (int p = 0; p < 4; p++) {
            int q = tid + p * 128;
            int t = q >> 2, cq = q & 3;
            float4 v = *(const float4*)&s_out[t * 16 + cq * 4];
            // exact GELU: x * 0.5 * (1 + erf(x / sqrt(2)))
            v.x = 0.5f * v.x * (1.0f + erff(v.x * 0.70710678118654752f));
            v.y = 0.5f * v.y * (1.0f + erff(v.y * 0.70710678118654752f));
            v.z = 0.5f * v.z * (1.0f + erff(v.z * 0.70710678118654752f));
            v.w = 0.5f * v.w * (1.0f + erff(v.w * 0.70710678118654752f));
            *(float4*)&yout[(l0 + t) * HH + ch0 + cq * 4] = v;
        }
        __syncthreads();
    }
}

// ---------------------------------------------------------------------------
// Fused 1x1 conv + GLU + residual:
//   y[m, o] = yg[m, :] . W[o, :] + b[o]  for o in [0,512)
//   z = y[:, n] * sigmoid(y[:, n+256]);  zr = z + h
// Tiles BM=64, BN=64 (both halves), BK=32; 256 threads; 4x4(+4x4) per thread.
// ---------------------------------------------------------------------------
__global__ __launch_bounds__(256) void gemm_glu_kernel(
        const float* __restrict__ Wq, const float* __restrict__ bias, int layer) {
    __shared__ float As[64][36];   // [row][k]
    __shared__ float Ba[32][68];   // [k][n]   a-half
    __shared__ float Bg[32][68];   // [k][n]   g-half
    int row0 = blockIdx.x * 64;
    int n0   = blockIdx.y * 64;
    const float* W  = Wq + (size_t)layer * 512 * HH;
    const float* bi = bias + layer * 512;
    int tid = threadIdx.x;
    int tx = tid & 15, ty = tid >> 4;
    float aa[4][4] = {}, ag[4][4] = {};
    for (int k0 = 0; k0 < HH; k0 += 32) {
        #pragma unroll
        for (int p = 0; p < 2; p++) {
            int q = tid + p * 256;
            int r = q >> 3, kq = q & 7;
            float4 v = *(const float4*)&g_yg[(size_t)(row0 + r) * HH + k0 + kq * 4];
            *(float4*)&As[r][kq * 4] = v;
        }
        #pragma unroll
        for (int p = 0; p < 2; p++) {
            int q = tid + p * 256;
            int r = q >> 3, kq = q & 7;
            float4 va = *(const float4*)&W[(size_t)(n0 + r) * HH + k0 + kq * 4];
            Ba[kq * 4 + 0][r] = va.x; Ba[kq * 4 + 1][r] = va.y;
            Ba[kq * 4 + 2][r] = va.z; Ba[kq * 4 + 3][r] = va.w;
            float4 vg = *(const float4*)&W[(size_t)(n0 + 256 + r) * HH + k0 + kq * 4];
            Bg[kq * 4 + 0][r] = vg.x; Bg[kq * 4 + 1][r] = vg.y;
            Bg[kq * 4 + 2][r] = vg.z; Bg[kq * 4 + 3][r] = vg.w;
        }
        __syncthreads();
        #pragma unroll
        for (int k = 0; k < 32; k++) {
            float a[4];
            #pragma unroll
            for (int i = 0; i < 4; i++) a[i] = As[ty * 4 + i][k];
            float4 bva = *(const float4*)&Ba[k][tx * 4];
            float4 bvg = *(const float4*)&Bg[k][tx * 4];
            float ba[4] = {bva.x, bva.y, bva.z, bva.w};
            float bg[4] = {bvg.x, bvg.y, bvg.z, bvg.w};
            #pragma unroll
            for (int i = 0; i < 4; i++) {
                #pragma unroll
                for (int jj = 0; jj < 4; jj++) {
                    aa[i][jj] = fmaf(a[i], ba[jj], aa[i][jj]);
                    ag[i][jj] = fmaf(a[i], bg[jj], ag[i][jj]);
                }
            }
        }
        __syncthreads();
    }
    #pragma unroll
    for (int i = 0; i < 4; i++) {
        int m = row0 + ty * 4 + i;
        #pragma unroll
        for (int jj = 0; jj < 4; jj++) {
            int n = n0 + tx * 4 + jj;
            float ya = aa[i][jj] + bi[n];
            float yg = ag[i][jj] + bi[n + 256];
            float z  = ya / (1.0f + expf(-yg));          // a * sigmoid(g)
            g_zr[(size_t)m * HH + n] = z + g_h[(size_t)m * HH + n];
        }
    }
}

// ---------------------------------------------------------------------------
// LayerNorm over H=256 (biased var, eps 1e-5): g_h = LN(g_zr)*gamma + beta
// One warp per row; block 256 -> 8 rows.
// ---------------------------------------------------------------------------
__global__ __launch_bounds__(256) void ln_kernel(
        const float* __restrict__ lng, const float* __restrict__ lnb, int layer) {
    int row  = blockIdx.x * 8 + (threadIdx.x >> 5);
    int lane = threadIdx.x & 31;
    const float* Z = g_zr + (size_t)row * HH;
    float4 v0 = *(const float4*)&Z[lane * 4];
    float4 v1 = *(const float4*)&Z[128 + lane * 4];
    float s  = v0.x + v0.y + v0.z + v0.w + v1.x + v1.y + v1.z + v1.w;
    float ss = v0.x*v0.x + v0.y*v0.y + v0.z*v0.z + v0.w*v0.w
             + v1.x*v1.x + v1.y*v1.y + v1.z*v1.z + v1.w*v1.w;
    #pragma unroll
    for (int o = 16; o; o >>= 1) {
        s  += __shfl_xor_sync(0xffffffffu, s,  o);
        ss += __shfl_xor_sync(0xffffffffu, ss, o);
    }
    float mean = s * (1.0f / 256.0f);
    float var  = ss * (1.0f / 256.0f) - mean * mean;
    float rstd = rsqrtf(var + 1e-5f);
    float* O = g_h + (size_t)row * HH;
    const float* G0 = &lng[layer * HH];
    const float* B0 = &lnb[layer * HH];
    float4 ga = *(const float4*)&G0[lane * 4];
    float4 gb = *(const float4*)&G0[128 + lane * 4];
    float4 ba = *(const float4*)&B0[lane * 4];
    float4 bb = *(const float4*)&B0[128 + lane * 4];
    float4 o0, o1;
    o0.x = (v0.x - mean) * rstd * ga.x + ba.x;
    o0.y = (v0.y - mean) * rstd * ga.y + ba.y;
    o0.z = (v0.z - mean) * rstd * ga.z + ba.z;
    o0.w = (v0.w - mean) * rstd * ga.w + ba.w;
    o1.x = (v1.x - mean) * rstd * gb.x + bb.x;
    o1.y = (v1.y - mean) * rstd * gb.y + bb.y;
    o1.z = (v1.z - mean) * rstd * gb.z + bb.z;
    o1.w = (v1.w - mean) * rstd * gb.w + bb.w;
    *(float4*)&O[lane * 4] = o0;
    *(float4*)&O[128 + lane * 4] = o1;
}

// ---------------------------------------------------------------------------
// Mean pool over L: g_pool[b, ch] = mean_l g_h[b, l, ch].  Deterministic
// (no atomics): one block per batch, thread per channel, 4 accumulators.
// ---------------------------------------------------------------------------
__global__ __launch_bounds__(256) void pool_kernel() {
    int b = blockIdx.x, ch = threadIdx.x;
    const float* Hp = g_h + (size_t)b * LL * HH + ch;
    float s0 = 0.f, s1 = 0.f, s2 = 0.f, s3 = 0.f;
    for (int l = 0; l < LL; l += 4) {
        s0 += Hp[(size_t)(l + 0) * HH];
        s1 += Hp[(size_t)(l + 1) * HH];
        s2 += Hp[(size_t)(l + 2) * HH];
        s3 += Hp[(size_t)(l + 3) * HH];
    }
    g_pool[b * HH + ch] = (s0 + s1 + s2 + s3) * (1.0f / LL);
}

// ---------------------------------------------------------------------------
// Decoder MLP: 256 -> 128 (relu) -> 64 (relu) -> 32.  One block per batch.
// ---------------------------------------------------------------------------
__global__ __launch_bounds__(128) void decoder_kernel(
        const float* __restrict__ w1, const float* __restrict__ b1,
        const float* __restrict__ w2, const float* __restrict__ b2,
        const float* __restrict__ w3, const float* __restrict__ b3,
        float* __restrict__ out) {
    __shared__ float p[HH];
    __shared__ float q1[DM1];
    __shared__ float q2[DM2];
    int b = blockIdx.x, tid = threadIdx.x;
    p[tid]       = g_pool[b * HH + tid];
    p[tid + 128] = g_pool[b * HH + tid + 128];
    __syncthreads();
    {
        float s = b1[tid];
        #pragma unroll 4
        for (int k = 0; k < HH; k++) s = fmaf(p[k], w1[k * DM1 + tid], s);
        q1[tid] = fmaxf(s, 0.0f);
    }
    __syncthreads();
    if (tid < DM2) {
        float s = b2[tid];
        #pragma unroll 4
        for (int k = 0; k < DM1; k++) s = fmaf(q1[k], w2[k * DM2 + tid], s);
        q2[tid] = fmaxf(s, 0.0f);
    }
    __syncthreads();
    if (tid < DOUT) {
        float s = b3[tid];
        #pragma unroll 4
        for (int k = 0; k < DM2; k++) s = fmaf(q2[k], w3[k * DOUT + tid], s);
        out[b * DOUT + tid] = s;
    }
}

// ---------------------------------------------------------------------------
extern "C" void kernel_launch(void* const* d_in, const int* in_sizes, int n_in,
                              void* d_out, int out_size) {
    const float* x          = (const float*)d_in[0];
    const float* enc_w      = (const float*)d_in[1];
    const float* enc_b      = (const float*)d_in[2];
    const float* log_dt     = (const float*)d_in[3];
    const float* C_re       = (const float*)d_in[4];
    const float* C_im       = (const float*)d_in[5];
    const float* log_A_real = (const float*)d_in[6];
    const float* A_imag     = (const float*)d_in[7];
    const float* D_skip     = (const float*)d_in[8];
    const float* w_out      = (const float*)d_in[9];
    const float* b_out      = (const float*)d_in[10];
    const float* ln_g       = (const float*)d_in[11];
    const float* ln_b       = (const float*)d_in[12];
    const float* dec_w1     = (const float*)d_in[13];
    const float* dec_b1     = (const float*)d_in[14];
    const float* dec_w2     = (const float*)d_in[15];
    const float* dec_b2     = (const float*)d_in[16];
    const float* dec_w3     = (const float*)d_in[17];
    const float* dec_b3     = (const float*)d_in[18];
    float* out = (float*)d_out;

    dim3 gemm_grid(BB * LL / 64, HH / 64);       // (512, 4)
    encoder_kernel<<<gemm_grid, 256>>>(x, enc_w, enc_b);
    for (int layer = 0; layer < NLAYERS; layer++) {
        scan_kernel<<<dim3(BB, HH / 16), 128>>>(log_dt, C_re, C_im,
                                                log_A_real, A_imag, D_skip, layer);
        gemm_glu_kernel<<<gemm_grid, 256>>>(w_out, b_out, layer);
        ln_kernel<<<BB * LL / 8, 256>>>(ln_g, ln_b, layer);
    }
    pool_kernel<<<BB, 256>>>();
    decoder_kernel<<<BB, 128>>>(dec_w1, dec_b1, dec_w2, dec_b2, dec_w3, dec_b3, out);
}